// round 16
// baseline (speedup 1.0000x reference)
#include <cuda_runtime.h>
#include <cstdint>
#include <cstddef>

#define BB 64
#define SS 2048
#define DIN 512
#define HH 1024
#define SPLITS 8                       // tiles per batch; 512 tiles total
#define NTILES (BB * SPLITS)
#define ROWS_PER_TILE (SS / SPLITS)    // 256
#define NWARP 16
#define RING_DEPTH 3
#define NJOBS 128                      // gemm jobs: 8 batch-groups x 16 h-chunks
#define GRIDN 152

#define NEG_INF __int_as_float(0xff800000)

// ---------------- scratch (no allocations allowed) ----------------
__device__ __align__(16) float g_x[BB * HH];            // inp@W + b
__device__ float          g_score[BB * SS];             // raw scores (-inf where masked)
__device__ __align__(16) float g_acc[NTILES * HH];      // tile partial weighted sums
__device__ float          g_l[NTILES];                  // tile partial sum-of-exp
__device__ unsigned       g_ticket;                     // work queue (jobs then tiles)
__device__ unsigned       g_jdone[8];                   // per-bg gemm-job completion
__device__ unsigned       g_bready[8];                  // per-bg x readiness flag
__device__ unsigned       g_bdone[BB];                  // per-batch tile completion
__device__ unsigned       g_exit;                       // exit counter (for resets)

// ---------------- helpers ----------------
__device__ __forceinline__ float tanh_fast(float x) {
    float y;
    asm("tanh.approx.f32 %0, %1;" : "=f"(y) : "f"(x));
    return y;
}

__device__ __forceinline__ void issue_row(const float* cb, int k, int n,
                                          unsigned slot_u32, int ln,
                                          const int* s_idx) {
    if (k < n) {
        const float* src = cb + (size_t)s_idx[k] * HH + ln * 4;
        unsigned dst = slot_u32 + ln * 16;
#pragma unroll
        for (int i = 0; i < 8; i++)
            asm volatile("cp.async.cg.shared.global [%0], [%1], 16;"
                         :: "r"(dst + i * 512), "l"(src + i * 128) : "memory");
    }
    asm volatile("cp.async.commit_group;" ::: "memory");
}

// ---------------- THE kernel: soft-pipelined gemm + attention ---------------
__global__ __launch_bounds__(512, 1) void fused_kernel(const float* __restrict__ inp,
                                                       const float* __restrict__ Wm,
                                                       const float* __restrict__ bias,
                                                       const void*  __restrict__ mraw,
                                                       const float* __restrict__ ctx,
                                                       const float* __restrict__ v,
                                                       float* __restrict__ out_applied,
                                                       float* __restrict__ out_w) {
    extern __shared__ float dsm[];
    float* xs   = dsm;                 // attention: HH floats
    float* ring = dsm + HH;            // attention: NWARP*RING_DEPTH*HH floats

    __shared__ int      s_idx[ROWS_PER_TILE];
    __shared__ int      s_wcnt[8];
    __shared__ float    s_l[NWARP];
    __shared__ unsigned s_tile;
    __shared__ int      s_last;

    int t  = threadIdx.x;
    int w  = t >> 5;
    int ln = t & 31;

    // ---- mask encoding detection (once per CTA; first 4KB, L2-hot) ----
    int mode;
    {
        const unsigned* wds = (const unsigned*)mraw;
        int notInt = 0, notFloat = 0;
        for (int i = t; i < 1024; i += 512) {
            unsigned x = wds[i];
            notInt   |= (x > 1u);
            notFloat |= (x != 0u && x != 0x3F800000u);
        }
        notInt   = __syncthreads_or(notInt);
        notFloat = __syncthreads_or(notFloat);
        mode = notInt ? (notFloat ? 2 : 1) : 0;   // 0:int32 1:float32 2:bytes
    }

    float4 vv[8];
    const float4* vr = (const float4*)v;
#pragma unroll
    for (int j = 0; j < 8; j++) vv[j] = __ldg(&vr[j * 32 + ln]);

    float* myring = ring + w * (RING_DEPTH * HH);
    unsigned ring_u32 = (unsigned)__cvta_generic_to_shared(myring);

    for (;;) {
        if (t == 0) s_tile = atomicAdd(&g_ticket, 1u);
        __syncthreads();               // orders prior ticket's smem reuse
        unsigned tk = s_tile;
        if (tk >= NJOBS + NTILES) break;

        if (tk < NJOBS) {
            // ================== GEMM job: x[b0..b0+8, h0..h0+64) ==========
            int bg = tk >> 4, hc = tk & 15;
            int b0 = bg * 8, h0 = hc * 64;

            float4* Ws4 = (float4*)dsm;              // [512][16] float4
            float4* Is4 = (float4*)(dsm + 32768);    // [8][128] float4
            float4* pt4 = (float4*)(dsm + 36864);    // [4][128] float4

            for (int i = t; i < 8192; i += 512) {    // W slab 128KB
                int k = i >> 4, hj = i & 15;
                Ws4[i] = *(const float4*)&Wm[(size_t)k * HH + h0 + hj * 4];
            }
            for (int i = t; i < 1024; i += 512) {    // inp rows 16KB
                int bb = i >> 7, k4 = i & 127;
                Is4[i] = *(const float4*)&inp[(b0 + bb) * DIN + k4 * 4];
            }
            __syncthreads();

            int kq = t >> 7, b = t & 7, hq = (t >> 3) & 15;
            float4 a = make_float4(0.f, 0.f, 0.f, 0.f);
            const float4* ib = Is4 + b * 128 + kq * 32;
            const float4* wb = Ws4 + (size_t)kq * 128 * 16 + hq;
#pragma unroll 8
            for (int k4 = 0; k4 < 32; k4++) {
                float4 iv = ib[k4];
                float4 w0 = wb[(4 * k4 + 0) * 16];
                float4 w1 = wb[(4 * k4 + 1) * 16];
                float4 w2 = wb[(4 * k4 + 2) * 16];
                float4 w3 = wb[(4 * k4 + 3) * 16];
                a.x = fmaf(iv.x, w0.x, a.x); a.y = fmaf(iv.x, w0.y, a.y);
                a.z = fmaf(iv.x, w0.z, a.z); a.w = fmaf(iv.x, w0.w, a.w);
                a.x = fmaf(iv.y, w1.x, a.x); a.y = fmaf(iv.y, w1.y, a.y);
                a.z = fmaf(iv.y, w1.z, a.z); a.w = fmaf(iv.y, w1.w, a.w);
                a.x = fmaf(iv.z, w2.x, a.x); a.y = fmaf(iv.z, w2.y, a.y);
                a.z = fmaf(iv.z, w2.z, a.z); a.w = fmaf(iv.z, w2.w, a.w);
                a.x = fmaf(iv.w, w3.x, a.x); a.y = fmaf(iv.w, w3.y, a.y);
                a.z = fmaf(iv.w, w3.z, a.z); a.w = fmaf(iv.w, w3.w, a.w);
            }
            pt4[kq * 128 + b * 16 + hq] = a;
            __syncthreads();

            if (t < 128) {                           // reduce 4 kq + bias
                int bb = t >> 4, hh = t & 15;
                float4 s0 = pt4[t], s1 = pt4[128 + t];
                float4 s2 = pt4[256 + t], s3 = pt4[384 + t];
                float4 bv = *(const float4*)&bias[h0 + hh * 4];
                float4 r;
                r.x = ((s0.x + s1.x) + (s2.x + s3.x)) + bv.x;
                r.y = ((s0.y + s1.y) + (s2.y + s3.y)) + bv.y;
                r.z = ((s0.z + s1.z) + (s2.z + s3.z)) + bv.z;
                r.w = ((s0.w + s1.w) + (s2.w + s3.w)) + bv.w;
                *(float4*)&g_x[(size_t)(b0 + bb) * HH + h0 + hh * 4] = r;
            }
            __syncthreads();                         // stores done before flag
            if (t == 0) {
                __threadfence();
                unsigned old = atomicAdd(&g_jdone[bg], 1u);
                if (old == 15) atomicExch(&g_bready[bg], 1u);  // release bg
            }
            continue;
        }

        // ==================== attention tile ===============================
        unsigned tile = tk - NJOBS;
        int b  = tile >> 3;            // SPLITS = 8
        int sp = tile & (SPLITS - 1);
        int rowbase = b * SS + sp * ROWS_PER_TILE;

        // ---- mask from raw + compact unmasked row indices ----
        unsigned char mk = 1;
        if (t < ROWS_PER_TILE) {
            int gi = rowbase + t;
            if (mode == 0)      mk = (((const int*)mraw)[gi] != 0);
            else if (mode == 1) mk = (((const float*)mraw)[gi] != 0.0f);
            else                mk = (((const unsigned char*)mraw)[gi] != 0);
        }
        unsigned bits = __ballot_sync(0xffffffffu, mk == 0);
        if (t < ROWS_PER_TILE && mk) g_score[rowbase + t] = NEG_INF;
        if (w < 8 && ln == 0) s_wcnt[w] = __popc(bits);
        __syncthreads();
        int n = 0;
#pragma unroll
        for (int i = 0; i < 8; i++) n += s_wcnt[i];
        if (t < ROWS_PER_TILE && !mk) {
            int basew = 0;
#pragma unroll
            for (int i = 0; i < 8; i++) if (i < w) basew += s_wcnt[i];
            s_idx[basew + __popc(bits & ((1u << ln) - 1u))] = t;
        }
        __syncthreads();

        // ---- prefetch first rows NOW (independent of x) ----
        const float* cb = ctx + (size_t)rowbase * HH;
        issue_row(cb, w,             n, ring_u32,          ln, s_idx);
        issue_row(cb, w + NWARP,     n, ring_u32 + HH * 4, ln, s_idx);
        issue_row(cb, w + 2 * NWARP, n, ring_u32 + HH * 8, ln, s_idx);

        // ---- wait for this batch-group's x (overlaps with prefetch) ----
        if (t == 0) {
            unsigned r;
            do {
                asm volatile("ld.acquire.gpu.global.b32 %0, [%1];"
                             : "=r"(r) : "l"(&g_bready[b >> 3]) : "memory");
            } while (!r);
        }
        __syncthreads();
        xs[t]       = g_x[b * HH + t];
        xs[t + 512] = g_x[b * HH + 512 + t];
        __syncthreads();

        // ---- per-warp row loop over compacted list (champion loop) ----
        float4 acc[8];
#pragma unroll
        for (int j = 0; j < 8; j++) acc[j] = make_float4(0.f, 0.f, 0.f, 0.f);
        float l = 0.f;

        int slot = 0;
        for (int k = w; k < n; k += NWARP) {
            asm volatile("cp.async.wait_group 2;" ::: "memory");
            const float* sp_ = myring + slot * HH;

            float part = 0.f;
#pragma unroll
            for (int j = 0; j < 8; j++) {
                float4 c  = *(const float4*)&sp_[j * 128 + ln * 4];
                float4 xj = *(const float4*)&xs[j * 128 + ln * 4];
                float4 vg = vv[j];
                part = fmaf(tanh_fast(xj.x + c.x), vg.x, part);
                part = fmaf(tanh_fast(xj.y + c.y), vg.y, part);
                part = fmaf(tanh_fast(xj.z + c.z), vg.z, part);
                part = fmaf(tanh_fast(xj.w + c.w), vg.w, part);
            }
#pragma unroll
            for (int off = 16; off; off >>= 1)
                part += __shfl_xor_sync(0xffffffffu, part, off);

            if (ln == 0) g_score[rowbase + s_idx[k]] = part;
            float p = __expf(part);    // fixed reference M=0: |score| < 40
            l += p;
#pragma unroll
            for (int j = 0; j < 8; j++) {          // re-read row (LDS, no spill)
                float4 c = *(const float4*)&sp_[j * 128 + ln * 4];
                acc[j].x = fmaf(c.x, p, acc[j].x);
                acc[j].y = fmaf(c.y, p, acc[j].y);
                acc[j].z = fmaf(c.z, p, acc[j].z);
                acc[j].w = fmaf(c.w, p, acc[j].w);
            }
            issue_row(cb, k + 3 * NWARP, n, ring_u32 + slot * HH * 4, ln, s_idx);
            slot = (slot == RING_DEPTH - 1) ? 0 : slot + 1;
        }
        asm volatile("cp.async.wait_group 0;" ::: "memory");

        // ---- CTA combine: overlay acc onto ring smem, tree-reduce ----
        if (ln == 0) s_l[w] = l;
        __syncthreads();
        float* sout = ring;
#pragma unroll
        for (int j = 0; j < 8; j++)
            *(float4*)&sout[w * HH + j * 128 + ln * 4] = acc[j];
        __syncthreads();

        float L = 0.f;
#pragma unroll
        for (int i = 0; i < NWARP; i++) L += s_l[i];
        float sum0 = 0.f, sum1 = 0.f;
#pragma unroll
        for (int i = 0; i < NWARP; i++) {
            sum0 += sout[i * HH + t];
            sum1 += sout[i * HH + t + 512];
        }
        g_acc[(size_t)tile * HH + t]       = sum0;
        g_acc[(size_t)tile * HH + t + 512] = sum1;
        if (t == 0) g_l[tile] = L;

        // ---- last tile of this batch? finalize the batch here ----
        __threadfence();
        if (t == 0) {
            unsigned old = atomicAdd(&g_bdone[b], 1u);
            s_last = (old == SPLITS - 1);
        }
        __syncthreads();
        if (s_last) {
            float Lb = 0.f;
#pragma unroll
            for (int i = 0; i < SPLITS; i++) Lb += __ldcg(&g_l[b * SPLITS + i]);
            float invL = 1.0f / Lb;
#pragma unroll
            for (int r = 0; r < 2; r++) {
                int h = t + r * 512;
                float s = 0.f;
#pragma unroll
                for (int i = 0; i < SPLITS; i++)
                    s += __ldcg(&g_acc[(size_t)(b * SPLITS + i) * HH + h]);
                out_applied[b * HH + h] = s * invL;
            }
#pragma unroll
            for (int r = 0; r < 4; r++) {
                int si = t + r * 512;
                float sc = __ldcg(&g_score[b * SS + si]);  // -inf masked -> 0
                out_w[b * SS + si] = __expf(sc) * invL;
            }
        }
    }

    // ---- exit: last CTA resets all persistent state for graph replay ----
    __syncthreads();
    if (t == 0) {
        __threadfence();
        unsigned old = atomicAdd(&g_exit, 1u);
        if (old == GRIDN - 1) {
            g_ticket = 0;
#pragma unroll
            for (int i = 0; i < 8; i++) { g_jdone[i] = 0; g_bready[i] = 0; }
#pragma unroll
            for (int i = 0; i < BB; i++) g_bdone[i] = 0;
            g_exit = 0;
        }
    }
}

// ---------------- launch ----------------
extern "C" void kernel_launch(void* const* d_in, const int* in_sizes, int n_in,
                              void* d_out, int out_size) {
    const float* inp  = (const float*)d_in[0];
    // d_in[1] = hidden (unused by the reference computation)
    const float* ctx  = (const float*)d_in[2];
    const void*  mask = d_in[3];
    const float* Wm   = (const float*)d_in[4];
    const float* bias = (const float*)d_in[5];
    const float* v    = (const float*)d_in[6];
    float* out = (float*)d_out;

    const int dyn_smem = (HH + NWARP * RING_DEPTH * HH) * (int)sizeof(float); // 200704
    cudaFuncSetAttribute(fused_kernel,
                         cudaFuncAttributeMaxDynamicSharedMemorySize, dyn_smem);

    fused_kernel<<<GRIDN, 512, dyn_smem>>>(inp, Wm, bias, mask, ctx, v,
                                           out, out + BB * HH);
}